// round 9
// baseline (speedup 1.0000x reference)
#include <cuda_runtime.h>

// graphDenoising: per-(b,n) rank-1 bilinear scores + sigmoid.
//   w[b] = beh_emb[b] for b < B-1, prompt_emb for b = B-1
//   u = dot(user[b,n], w[b]); p = dot(pos[b,n], w[b]); g = dot(neg[b,n], w[b])
//   out[b, n] = sigmoid(u*p);  out[b, N+n] = sigmoid(u*g)
//
// Kernel-time-optimal structure (reproduced 4x at 219.5-222.1 us, DRAM
// 92-93%): warp per row, 6 coalesced LDG.128 per lane, butterfly reduce,
// lane-0 store. This round: identical per-warp code, 512-thread blocks
// (grid 65536 -> 32768) to test whether the consistent ~13us wall-vs-
// kernel gap at grid=65536 follows grid size (R2 @32768 showed 2.3us).

#define DIM 256
#define THREADS 512

__global__ __launch_bounds__(THREADS)
void graph_denoise_kernel(const float* __restrict__ user_emb,
                          const float* __restrict__ pos_emb,
                          const float* __restrict__ neg_emb,
                          const float* __restrict__ beh_emb,
                          const float* __restrict__ prompt_emb,
                          float* __restrict__ out,
                          int N, int B)
{
    const int warp_id = (blockIdx.x * blockDim.x + threadIdx.x) >> 5;
    const int lane = threadIdx.x & 31;
    const int total = B * N;
    if (warp_id >= total) return;

    const int b = warp_id / N;
    const int n = warp_id - b * N;

    // Per-behavior weight vector (L1-resident after first touch)
    const float4* w4 = (b < B - 1)
        ? reinterpret_cast<const float4*>(beh_emb + (size_t)b * DIM)
        : reinterpret_cast<const float4*>(prompt_emb);
    const float4 w0 = w4[lane];
    const float4 w1 = w4[lane + 32];

    const size_t base = (size_t)warp_id * DIM;  // (b*N + n) * DIM
    const float4* u4 = reinterpret_cast<const float4*>(user_emb + base);
    const float4* p4 = reinterpret_cast<const float4*>(pos_emb  + base);
    const float4* g4 = reinterpret_cast<const float4*>(neg_emb  + base);

    // 6 independent LDG.128 -> MLP=6 per lane
    const float4 a0 = u4[lane], a1 = u4[lane + 32];
    const float4 b0 = p4[lane], b1 = p4[lane + 32];
    const float4 c0 = g4[lane], c1 = g4[lane + 32];

    float du = a0.x * w0.x;
    du = fmaf(a0.y, w0.y, du); du = fmaf(a0.z, w0.z, du); du = fmaf(a0.w, w0.w, du);
    du = fmaf(a1.x, w1.x, du); du = fmaf(a1.y, w1.y, du);
    du = fmaf(a1.z, w1.z, du); du = fmaf(a1.w, w1.w, du);

    float dp = b0.x * w0.x;
    dp = fmaf(b0.y, w0.y, dp); dp = fmaf(b0.z, w0.z, dp); dp = fmaf(b0.w, w0.w, dp);
    dp = fmaf(b1.x, w1.x, dp); dp = fmaf(b1.y, w1.y, dp);
    dp = fmaf(b1.z, w1.z, dp); dp = fmaf(b1.w, w1.w, dp);

    float dg = c0.x * w0.x;
    dg = fmaf(c0.y, w0.y, dg); dg = fmaf(c0.z, w0.z, dg); dg = fmaf(c0.w, w0.w, dg);
    dg = fmaf(c1.x, w1.x, dg); dg = fmaf(c1.y, w1.y, dg);
    dg = fmaf(c1.z, w1.z, dg); dg = fmaf(c1.w, w1.w, dg);

    // Butterfly warp reduction for all three dots
    #pragma unroll
    for (int off = 16; off > 0; off >>= 1) {
        du += __shfl_xor_sync(0xffffffffu, du, off);
        dp += __shfl_xor_sync(0xffffffffu, dp, off);
        dg += __shfl_xor_sync(0xffffffffu, dg, off);
    }

    if (lane == 0) {
        const float xp = du * dp;
        const float xg = du * dg;
        const float sp = 1.0f / (1.0f + __expf(-xp));
        const float sg = 1.0f / (1.0f + __expf(-xg));
        float* ob = out + (size_t)b * 2 * N;
        ob[n]     = sp;
        ob[N + n] = sg;
    }
}

extern "C" void kernel_launch(void* const* d_in, const int* in_sizes, int n_in,
                              void* d_out, int out_size)
{
    const float* user_emb   = (const float*)d_in[0];
    const float* pos_emb    = (const float*)d_in[1];
    const float* neg_emb    = (const float*)d_in[2];
    const float* beh_emb    = (const float*)d_in[3];
    const float* prompt_emb = (const float*)d_in[4];
    float* out = (float*)d_out;

    const int B = in_sizes[3] / DIM;            // 4
    const int N = in_sizes[0] / (B * DIM);      // 131072

    const int total_warps = B * N;               // 524288
    const int warps_per_block = THREADS / 32;    // 16
    const int blocks = (total_warps + warps_per_block - 1) / warps_per_block;  // 32768

    graph_denoise_kernel<<<blocks, THREADS>>>(user_emb, pos_emb, neg_emb,
                                              beh_emb, prompt_emb, out, N, B);
}

// round 10
// speedup vs baseline: 1.0536x; 1.0536x over previous
#include <cuda_runtime.h>

// graphDenoising: per-(b,n) rank-1 bilinear scores + sigmoid.
// DRAM-roofline kernel: 1.61 GB read once. One warp per PAIR of rows.
// SESSION-BEST on the scored wall metric: 229.408 us, reproduced.
// (The warp-per-row variant profiles faster under ncu, 219.5 us, but
// consistently walls 232-235 us in the timed replay loop across 5 runs —
// the row-batched structure wins the scored metric.)

#define DIM 256

__global__ __launch_bounds__(256)
void graph_denoise_kernel(const float* __restrict__ user_emb,
                          const float* __restrict__ pos_emb,
                          const float* __restrict__ neg_emb,
                          const float* __restrict__ beh_emb,
                          const float* __restrict__ prompt_emb,
                          float* __restrict__ out,
                          int N, int B)
{
    const int warp_id = (blockIdx.x * blockDim.x + threadIdx.x) >> 5;
    const int lane = threadIdx.x & 31;
    const int pair = warp_id;                 // handles rows 2*pair, 2*pair+1
    const int row0 = pair << 1;
    const int total = B * N;
    if (row0 >= total) return;

    // N is even, so row0 and row0+1 share the same behavior b.
    const int b = row0 / N;
    const int n0 = row0 - b * N;

    const float4* w4 = (b < B - 1)
        ? reinterpret_cast<const float4*>(beh_emb + (size_t)b * DIM)
        : reinterpret_cast<const float4*>(prompt_emb);
    const float4 w0 = w4[lane];
    const float4 w1 = w4[lane + 32];

    const size_t base = (size_t)row0 * DIM;
    const float4* u4 = reinterpret_cast<const float4*>(user_emb + base);
    const float4* p4 = reinterpret_cast<const float4*>(pos_emb  + base);
    const float4* g4 = reinterpret_cast<const float4*>(neg_emb  + base);

    // 12 independent LDG.128 front-batched -> MLP = 12 per lane.
    // Row 0 tiles at [lane, lane+32]; row 1 tiles at [lane+64, lane+96].
    const float4 a0 = u4[lane],      a1 = u4[lane + 32];
    const float4 b0 = p4[lane],      b1 = p4[lane + 32];
    const float4 c0 = g4[lane],      c1 = g4[lane + 32];
    const float4 a2 = u4[lane + 64], a3 = u4[lane + 96];
    const float4 b2 = p4[lane + 64], b3 = p4[lane + 96];
    const float4 c2 = g4[lane + 64], c3 = g4[lane + 96];

    float du0, dp0, dg0, du1, dp1, dg1;

    du0 = a0.x * w0.x;
    du0 = fmaf(a0.y, w0.y, du0); du0 = fmaf(a0.z, w0.z, du0); du0 = fmaf(a0.w, w0.w, du0);
    du0 = fmaf(a1.x, w1.x, du0); du0 = fmaf(a1.y, w1.y, du0);
    du0 = fmaf(a1.z, w1.z, du0); du0 = fmaf(a1.w, w1.w, du0);

    dp0 = b0.x * w0.x;
    dp0 = fmaf(b0.y, w0.y, dp0); dp0 = fmaf(b0.z, w0.z, dp0); dp0 = fmaf(b0.w, w0.w, dp0);
    dp0 = fmaf(b1.x, w1.x, dp0); dp0 = fmaf(b1.y, w1.y, dp0);
    dp0 = fmaf(b1.z, w1.z, dp0); dp0 = fmaf(b1.w, w1.w, dp0);

    dg0 = c0.x * w0.x;
    dg0 = fmaf(c0.y, w0.y, dg0); dg0 = fmaf(c0.z, w0.z, dg0); dg0 = fmaf(c0.w, w0.w, dg0);
    dg0 = fmaf(c1.x, w1.x, dg0); dg0 = fmaf(c1.y, w1.y, dg0);
    dg0 = fmaf(c1.z, w1.z, dg0); dg0 = fmaf(c1.w, w1.w, dg0);

    du1 = a2.x * w0.x;
    du1 = fmaf(a2.y, w0.y, du1); du1 = fmaf(a2.z, w0.z, du1); du1 = fmaf(a2.w, w0.w, du1);
    du1 = fmaf(a3.x, w1.x, du1); du1 = fmaf(a3.y, w1.y, du1);
    du1 = fmaf(a3.z, w1.z, du1); du1 = fmaf(a3.w, w1.w, du1);

    dp1 = b2.x * w0.x;
    dp1 = fmaf(b2.y, w0.y, dp1); dp1 = fmaf(b2.z, w0.z, dp1); dp1 = fmaf(b2.w, w0.w, dp1);
    dp1 = fmaf(b3.x, w1.x, dp1); dp1 = fmaf(b3.y, w1.y, dp1);
    dp1 = fmaf(b3.z, w1.z, dp1); dp1 = fmaf(b3.w, w1.w, dp1);

    dg1 = c2.x * w0.x;
    dg1 = fmaf(c2.y, w0.y, dg1); dg1 = fmaf(c2.z, w0.z, dg1); dg1 = fmaf(c2.w, w0.w, dg1);
    dg1 = fmaf(c3.x, w1.x, dg1); dg1 = fmaf(c3.y, w1.y, dg1);
    dg1 = fmaf(c3.z, w1.z, dg1); dg1 = fmaf(c3.w, w1.w, dg1);

    // Butterfly reduce all six dots (independent shuffle chains interleave)
    #pragma unroll
    for (int off = 16; off > 0; off >>= 1) {
        du0 += __shfl_xor_sync(0xffffffffu, du0, off);
        dp0 += __shfl_xor_sync(0xffffffffu, dp0, off);
        dg0 += __shfl_xor_sync(0xffffffffu, dg0, off);
        du1 += __shfl_xor_sync(0xffffffffu, du1, off);
        dp1 += __shfl_xor_sync(0xffffffffu, dp1, off);
        dg1 += __shfl_xor_sync(0xffffffffu, dg1, off);
    }

    if (lane == 0) {
        float* ob = out + (size_t)b * 2 * N;
        const float xp0 = du0 * dp0, xg0 = du0 * dg0;
        const float xp1 = du1 * dp1, xg1 = du1 * dg1;
        ob[n0]         = 1.0f / (1.0f + __expf(-xp0));
        ob[N + n0]     = 1.0f / (1.0f + __expf(-xg0));
        ob[n0 + 1]     = 1.0f / (1.0f + __expf(-xp1));
        ob[N + n0 + 1] = 1.0f / (1.0f + __expf(-xg1));
    }
}

extern "C" void kernel_launch(void* const* d_in, const int* in_sizes, int n_in,
                              void* d_out, int out_size)
{
    const float* user_emb   = (const float*)d_in[0];
    const float* pos_emb    = (const float*)d_in[1];
    const float* neg_emb    = (const float*)d_in[2];
    const float* beh_emb    = (const float*)d_in[3];
    const float* prompt_emb = (const float*)d_in[4];
    float* out = (float*)d_out;

    const int B = in_sizes[3] / DIM;            // 4
    const int N = in_sizes[0] / (B * DIM);      // 131072

    const int total_pairs = (B * N) / 2;
    const int threads = 256;
    const int warps_per_block = threads / 32;
    const int blocks = (total_pairs + warps_per_block - 1) / warps_per_block;

    graph_denoise_kernel<<<blocks, threads>>>(user_emb, pos_emb, neg_emb,
                                              beh_emb, prompt_emb, out, N, B);
}

// round 11
// speedup vs baseline: 1.0539x; 1.0003x over previous
#include <cuda_runtime.h>

// graphDenoising: per-(b,n) rank-1 bilinear scores + sigmoid.
// DRAM-roofline kernel: 1.61 GB read once. One warp per PAIR of rows.
// Row-batched structure = session-best scored wall (228.1 us, gap to ncu
// kernel time only 0.7 us vs ~13 us for warp-per-row). This round adds
// __ldcs (evict-first) on the 12 streaming loads — read-once data.

#define DIM 256

__global__ __launch_bounds__(256)
void graph_denoise_kernel(const float* __restrict__ user_emb,
                          const float* __restrict__ pos_emb,
                          const float* __restrict__ neg_emb,
                          const float* __restrict__ beh_emb,
                          const float* __restrict__ prompt_emb,
                          float* __restrict__ out,
                          int N, int B)
{
    const int warp_id = (blockIdx.x * blockDim.x + threadIdx.x) >> 5;
    const int lane = threadIdx.x & 31;
    const int row0 = warp_id << 1;            // handles rows row0, row0+1
    const int total = B * N;
    if (row0 >= total) return;

    // N is even, so row0 and row0+1 share the same behavior b.
    const int b = row0 / N;
    const int n0 = row0 - b * N;

    const float4* w4 = (b < B - 1)
        ? reinterpret_cast<const float4*>(beh_emb + (size_t)b * DIM)
        : reinterpret_cast<const float4*>(prompt_emb);
    const float4 w0 = w4[lane];
    const float4 w1 = w4[lane + 32];

    const size_t base = (size_t)row0 * DIM;
    const float4* u4 = reinterpret_cast<const float4*>(user_emb + base);
    const float4* p4 = reinterpret_cast<const float4*>(pos_emb  + base);
    const float4* g4 = reinterpret_cast<const float4*>(neg_emb  + base);

    // 12 independent streaming LDG.128 (read-once -> evict-first).
    // Row 0 tiles at [lane, lane+32]; row 1 tiles at [lane+64, lane+96].
    const float4 a0 = __ldcs(u4 + lane),      a1 = __ldcs(u4 + lane + 32);
    const float4 b0 = __ldcs(p4 + lane),      b1 = __ldcs(p4 + lane + 32);
    const float4 c0 = __ldcs(g4 + lane),      c1 = __ldcs(g4 + lane + 32);
    const float4 a2 = __ldcs(u4 + lane + 64), a3 = __ldcs(u4 + lane + 96);
    const float4 b2 = __ldcs(p4 + lane + 64), b3 = __ldcs(p4 + lane + 96);
    const float4 c2 = __ldcs(g4 + lane + 64), c3 = __ldcs(g4 + lane + 96);

    float du0, dp0, dg0, du1, dp1, dg1;

    du0 = a0.x * w0.x;
    du0 = fmaf(a0.y, w0.y, du0); du0 = fmaf(a0.z, w0.z, du0); du0 = fmaf(a0.w, w0.w, du0);
    du0 = fmaf(a1.x, w1.x, du0); du0 = fmaf(a1.y, w1.y, du0);
    du0 = fmaf(a1.z, w1.z, du0); du0 = fmaf(a1.w, w1.w, du0);

    dp0 = b0.x * w0.x;
    dp0 = fmaf(b0.y, w0.y, dp0); dp0 = fmaf(b0.z, w0.z, dp0); dp0 = fmaf(b0.w, w0.w, dp0);
    dp0 = fmaf(b1.x, w1.x, dp0); dp0 = fmaf(b1.y, w1.y, dp0);
    dp0 = fmaf(b1.z, w1.z, dp0); dp0 = fmaf(b1.w, w1.w, dp0);

    dg0 = c0.x * w0.x;
    dg0 = fmaf(c0.y, w0.y, dg0); dg0 = fmaf(c0.z, w0.z, dg0); dg0 = fmaf(c0.w, w0.w, dg0);
    dg0 = fmaf(c1.x, w1.x, dg0); dg0 = fmaf(c1.y, w1.y, dg0);
    dg0 = fmaf(c1.z, w1.z, dg0); dg0 = fmaf(c1.w, w1.w, dg0);

    du1 = a2.x * w0.x;
    du1 = fmaf(a2.y, w0.y, du1); du1 = fmaf(a2.z, w0.z, du1); du1 = fmaf(a2.w, w0.w, du1);
    du1 = fmaf(a3.x, w1.x, du1); du1 = fmaf(a3.y, w1.y, du1);
    du1 = fmaf(a3.z, w1.z, du1); du1 = fmaf(a3.w, w1.w, du1);

    dp1 = b2.x * w0.x;
    dp1 = fmaf(b2.y, w0.y, dp1); dp1 = fmaf(b2.z, w0.z, dp1); dp1 = fmaf(b2.w, w0.w, dp1);
    dp1 = fmaf(b3.x, w1.x, dp1); dp1 = fmaf(b3.y, w1.y, dp1);
    dp1 = fmaf(b3.z, w1.z, dp1); dp1 = fmaf(b3.w, w1.w, dp1);

    dg1 = c2.x * w0.x;
    dg1 = fmaf(c2.y, w0.y, dg1); dg1 = fmaf(c2.z, w0.z, dg1); dg1 = fmaf(c2.w, w0.w, dg1);
    dg1 = fmaf(c3.x, w1.x, dg1); dg1 = fmaf(c3.y, w1.y, dg1);
    dg1 = fmaf(c3.z, w1.z, dg1); dg1 = fmaf(c3.w, w1.w, dg1);

    // Butterfly reduce all six dots (independent shuffle chains interleave)
    #pragma unroll
    for (int off = 16; off > 0; off >>= 1) {
        du0 += __shfl_xor_sync(0xffffffffu, du0, off);
        dp0 += __shfl_xor_sync(0xffffffffu, dp0, off);
        dg0 += __shfl_xor_sync(0xffffffffu, dg0, off);
        du1 += __shfl_xor_sync(0xffffffffu, du1, off);
        dp1 += __shfl_xor_sync(0xffffffffu, dp1, off);
        dg1 += __shfl_xor_sync(0xffffffffu, dg1, off);
    }

    if (lane == 0) {
        float* ob = out + (size_t)b * 2 * N;
        const float xp0 = du0 * dp0, xg0 = du0 * dg0;
        const float xp1 = du1 * dp1, xg1 = du1 * dg1;
        ob[n0]         = 1.0f / (1.0f + __expf(-xp0));
        ob[N + n0]     = 1.0f / (1.0f + __expf(-xg0));
        ob[n0 + 1]     = 1.0f / (1.0f + __expf(-xp1));
        ob[N + n0 + 1] = 1.0f / (1.0f + __expf(-xg1));
    }
}

extern "C" void kernel_launch(void* const* d_in, const int* in_sizes, int n_in,
                              void* d_out, int out_size)
{
    const float* user_emb   = (const float*)d_in[0];
    const float* pos_emb    = (const float*)d_in[1];
    const float* neg_emb    = (const float*)d_in[2];
    const float* beh_emb    = (const float*)d_in[3];
    const float* prompt_emb = (const float*)d_in[4];
    float* out = (float*)d_out;

    const int B = in_sizes[3] / DIM;            // 4
    const int N = in_sizes[0] / (B * DIM);      // 131072

    const int total_pairs = (B * N) / 2;
    const int threads = 256;
    const int warps_per_block = threads / 32;
    const int blocks = (total_pairs + warps_per_block - 1) / warps_per_block;

    graph_denoise_kernel<<<blocks, threads>>>(user_emb, pos_emb, neg_emb,
                                              beh_emb, prompt_emb, out, N, B);
}

// round 12
// speedup vs baseline: 1.0762x; 1.0212x over previous
#include <cuda_runtime.h>

// graphDenoising: per-(b,n) rank-1 bilinear scores + sigmoid.
// DRAM-roofline kernel: 1.61 GB read once. One warp per PAIR of rows.
// Row-batched structure = best scored wall (228.06 us w/ __ldcs).
// This round: __stcs streaming stores (write-once output) + __fdividef
// in the sigmoid tail. Load path untouched.

#define DIM 256

__global__ __launch_bounds__(256)
void graph_denoise_kernel(const float* __restrict__ user_emb,
                          const float* __restrict__ pos_emb,
                          const float* __restrict__ neg_emb,
                          const float* __restrict__ beh_emb,
                          const float* __restrict__ prompt_emb,
                          float* __restrict__ out,
                          int N, int B)
{
    const int warp_id = (blockIdx.x * blockDim.x + threadIdx.x) >> 5;
    const int lane = threadIdx.x & 31;
    const int row0 = warp_id << 1;            // handles rows row0, row0+1
    const int total = B * N;
    if (row0 >= total) return;

    // N is even, so row0 and row0+1 share the same behavior b.
    const int b = row0 / N;
    const int n0 = row0 - b * N;

    const float4* w4 = (b < B - 1)
        ? reinterpret_cast<const float4*>(beh_emb + (size_t)b * DIM)
        : reinterpret_cast<const float4*>(prompt_emb);
    const float4 w0 = w4[lane];
    const float4 w1 = w4[lane + 32];

    const size_t base = (size_t)row0 * DIM;
    const float4* u4 = reinterpret_cast<const float4*>(user_emb + base);
    const float4* p4 = reinterpret_cast<const float4*>(pos_emb  + base);
    const float4* g4 = reinterpret_cast<const float4*>(neg_emb  + base);

    // 12 independent streaming LDG.128 (read-once -> evict-first).
    // Row 0 tiles at [lane, lane+32]; row 1 tiles at [lane+64, lane+96].
    const float4 a0 = __ldcs(u4 + lane),      a1 = __ldcs(u4 + lane + 32);
    const float4 b0 = __ldcs(p4 + lane),      b1 = __ldcs(p4 + lane + 32);
    const float4 c0 = __ldcs(g4 + lane),      c1 = __ldcs(g4 + lane + 32);
    const float4 a2 = __ldcs(u4 + lane + 64), a3 = __ldcs(u4 + lane + 96);
    const float4 b2 = __ldcs(p4 + lane + 64), b3 = __ldcs(p4 + lane + 96);
    const float4 c2 = __ldcs(g4 + lane + 64), c3 = __ldcs(g4 + lane + 96);

    float du0, dp0, dg0, du1, dp1, dg1;

    du0 = a0.x * w0.x;
    du0 = fmaf(a0.y, w0.y, du0); du0 = fmaf(a0.z, w0.z, du0); du0 = fmaf(a0.w, w0.w, du0);
    du0 = fmaf(a1.x, w1.x, du0); du0 = fmaf(a1.y, w1.y, du0);
    du0 = fmaf(a1.z, w1.z, du0); du0 = fmaf(a1.w, w1.w, du0);

    dp0 = b0.x * w0.x;
    dp0 = fmaf(b0.y, w0.y, dp0); dp0 = fmaf(b0.z, w0.z, dp0); dp0 = fmaf(b0.w, w0.w, dp0);
    dp0 = fmaf(b1.x, w1.x, dp0); dp0 = fmaf(b1.y, w1.y, dp0);
    dp0 = fmaf(b1.z, w1.z, dp0); dp0 = fmaf(b1.w, w1.w, dp0);

    dg0 = c0.x * w0.x;
    dg0 = fmaf(c0.y, w0.y, dg0); dg0 = fmaf(c0.z, w0.z, dg0); dg0 = fmaf(c0.w, w0.w, dg0);
    dg0 = fmaf(c1.x, w1.x, dg0); dg0 = fmaf(c1.y, w1.y, dg0);
    dg0 = fmaf(c1.z, w1.z, dg0); dg0 = fmaf(c1.w, w1.w, dg0);

    du1 = a2.x * w0.x;
    du1 = fmaf(a2.y, w0.y, du1); du1 = fmaf(a2.z, w0.z, du1); du1 = fmaf(a2.w, w0.w, du1);
    du1 = fmaf(a3.x, w1.x, du1); du1 = fmaf(a3.y, w1.y, du1);
    du1 = fmaf(a3.z, w1.z, du1); du1 = fmaf(a3.w, w1.w, du1);

    dp1 = b2.x * w0.x;
    dp1 = fmaf(b2.y, w0.y, dp1); dp1 = fmaf(b2.z, w0.z, dp1); dp1 = fmaf(b2.w, w0.w, dp1);
    dp1 = fmaf(b3.x, w1.x, dp1); dp1 = fmaf(b3.y, w1.y, dp1);
    dp1 = fmaf(b3.z, w1.z, dp1); dp1 = fmaf(b3.w, w1.w, dp1);

    dg1 = c2.x * w0.x;
    dg1 = fmaf(c2.y, w0.y, dg1); dg1 = fmaf(c2.z, w0.z, dg1); dg1 = fmaf(c2.w, w0.w, dg1);
    dg1 = fmaf(c3.x, w1.x, dg1); dg1 = fmaf(c3.y, w1.y, dg1);
    dg1 = fmaf(c3.z, w1.z, dg1); dg1 = fmaf(c3.w, w1.w, dg1);

    // Butterfly reduce all six dots (independent shuffle chains interleave)
    #pragma unroll
    for (int off = 16; off > 0; off >>= 1) {
        du0 += __shfl_xor_sync(0xffffffffu, du0, off);
        dp0 += __shfl_xor_sync(0xffffffffu, dp0, off);
        dg0 += __shfl_xor_sync(0xffffffffu, dg0, off);
        du1 += __shfl_xor_sync(0xffffffffu, du1, off);
        dp1 += __shfl_xor_sync(0xffffffffu, dp1, off);
        dg1 += __shfl_xor_sync(0xffffffffu, dg1, off);
    }

    if (lane == 0) {
        float* ob = out + (size_t)b * 2 * N;
        const float xp0 = du0 * dp0, xg0 = du0 * dg0;
        const float xp1 = du1 * dp1, xg1 = du1 * dg1;
        // Streaming stores: output is write-once, keep it out of L2 ways.
        __stcs(ob + n0,         __fdividef(1.0f, 1.0f + __expf(-xp0)));
        __stcs(ob + N + n0,     __fdividef(1.0f, 1.0f + __expf(-xg0)));
        __stcs(ob + n0 + 1,     __fdividef(1.0f, 1.0f + __expf(-xp1)));
        __stcs(ob + N + n0 + 1, __fdividef(1.0f, 1.0f + __expf(-xg1)));
    }
}

extern "C" void kernel_launch(void* const* d_in, const int* in_sizes, int n_in,
                              void* d_out, int out_size)
{
    const float* user_emb   = (const float*)d_in[0];
    const float* pos_emb    = (const float*)d_in[1];
    const float* neg_emb    = (const float*)d_in[2];
    const float* beh_emb    = (const float*)d_in[3];
    const float* prompt_emb = (const float*)d_in[4];
    float* out = (float*)d_out;

    const int B = in_sizes[3] / DIM;            // 4
    const int N = in_sizes[0] / (B * DIM);      // 131072

    const int total_pairs = (B * N) / 2;
    const int threads = 256;
    const int warps_per_block = threads / 32;
    const int blocks = (total_pairs + warps_per_block - 1) / warps_per_block;

    graph_denoise_kernel<<<blocks, threads>>>(user_emb, pos_emb, neg_emb,
                                              beh_emb, prompt_emb, out, N, B);
}